// round 13
// baseline (speedup 1.0000x reference)
#include <cuda_runtime.h>
#include <math.h>

// ---- problem constants ----
#define F      128
#define F3     384
#define NRBF   20
#define NATOMS 8000
#define NEDGES 160000
#define NMOLS  100
#define NCONV  3
#define CUTOFF 5.0f

#define TA  8    // atoms per half in upd kernel (16 per block)
#define TAM 4    // atoms per block in msg kernel
#define CAP 64   // max active edges per destination atom
#define MT  16   // atoms per block in phi mma kernel (one m16 tile)
#define PAD 132  // padded smem row

// ---- device scratch ----
__device__ float g_s   [NATOMS * F];
__device__ float g_v   [NATOMS * F3];
__device__ float g_ds  [NATOMS * F];
__device__ float g_dv  [NATOMS * F3];
__device__ float g_phi [NATOMS * F3];
__device__ float g_rbf [NEDGES * NRBF];   // env-premultiplied
__device__ float g_env [NEDGES];
__device__ float g_unit[NEDGES * 3];
__device__ int   g_cnt [NATOMS];
__device__ int   g_list[NATOMS * CAP];
// tf32 hi/lo split of msg MLP weights (all convs)
__device__ float g_w1hi[NCONV * F * F],  g_w1lo[NCONV * F * F];
__device__ float g_w2hi[NCONV * F * F3], g_w2lo[NCONV * F * F3];

__device__ __forceinline__ float silu(float x) { return x / (1.0f + __expf(-x)); }

// packed fp32x2 helpers
#define FFMA2(acc, a, b) asm("fma.rn.f32x2 %0, %1, %2, %0;" : "+l"(acc) : "l"(a), "l"(b))
__device__ __forceinline__ unsigned long long pk2(float x, float y) {
    unsigned long long r; asm("mov.b64 %0, {%1, %2};" : "=l"(r) : "f"(x), "f"(y)); return r;
}
__device__ __forceinline__ float2 upk2(unsigned long long v) {
    float2 o; asm("mov.b64 {%0, %1}, %2;" : "=f"(o.x), "=f"(o.y) : "l"(v)); return o;
}

// tf32 helpers
__device__ __forceinline__ unsigned tf32_cvt(float x) {
    unsigned r; asm("cvt.rna.tf32.f32 %0, %1;" : "=r"(r) : "f"(x)); return r;
}
__device__ __forceinline__ void mma_tf32(float* d,
    unsigned a0, unsigned a1, unsigned a2, unsigned a3,
    unsigned b0, unsigned b1)
{
    asm("mma.sync.aligned.m16n8k8.row.col.f32.tf32.tf32.f32 "
        "{%0,%1,%2,%3}, {%4,%5,%6,%7}, {%8,%9}, {%0,%1,%2,%3};"
        : "+f"(d[0]), "+f"(d[1]), "+f"(d[2]), "+f"(d[3])
        : "r"(a0), "r"(a1), "r"(a2), "r"(a3), "r"(b0), "r"(b1));
}

// ---------------------------------------------------------------------------
// init
// ---------------------------------------------------------------------------
__global__ void k_init(const float* __restrict__ emb, const int* __restrict__ z)
{
    int a = blockIdx.x, f = threadIdx.x;
    g_s[a * F + f] = emb[z[a] * F + f];
    int b = a * F3 + f * 3;
    g_v[b] = 0.0f; g_v[b + 1] = 0.0f; g_v[b + 2] = 0.0f;
    if (f == 0) g_cnt[a] = 0;
}

// ---------------------------------------------------------------------------
// split msg MLP weights into tf32 hi/lo (run once)
// ---------------------------------------------------------------------------
__global__ void k_split(const float* __restrict__ w1, const float* __restrict__ w2)
{
    int i = blockIdx.x * 256 + threadIdx.x;
    if (i < NCONV * F * F) {
        float w = w1[i];
        unsigned h = tf32_cvt(w);
        g_w1hi[i] = __uint_as_float(h);
        g_w1lo[i] = __uint_as_float(tf32_cvt(w - __uint_as_float(h)));
    }
    if (i < NCONV * F * F3) {
        float w = w2[i];
        unsigned h = tf32_cvt(w);
        g_w2hi[i] = __uint_as_float(h);
        g_w2lo[i] = __uint_as_float(tf32_cvt(w - __uint_as_float(h)));
    }
}

// ---------------------------------------------------------------------------
// edge geometry + CSR build
// ---------------------------------------------------------------------------
__global__ void k_edges(const float* __restrict__ xyz, const int* __restrict__ nbrs, int E)
{
    int e = blockIdx.x * 256 + threadIdx.x;
    if (e >= E) return;
    int i = nbrs[2 * e], j = nbrs[2 * e + 1];
    float rx = xyz[3 * j]     - xyz[3 * i];
    float ry = xyz[3 * j + 1] - xyz[3 * i + 1];
    float rz = xyz[3 * j + 2] - xyz[3 * i + 2];
    float d  = sqrtf(rx * rx + ry * ry + rz * rz);
    float inv = 1.0f / d;
    float t = d * (1.0f / CUTOFF);
    if (d <= CUTOFF) {
        float env = 0.5f * (cospif(t) + 1.0f);
        g_env[e] = env;
        g_unit[3 * e]     = rx * inv;
        g_unit[3 * e + 1] = ry * inv;
        g_unit[3 * e + 2] = rz * inv;
        float s = env * inv;
        #pragma unroll
        for (int k = 0; k < NRBF; k++)
            g_rbf[e * NRBF + k] = sinpif((float)(k + 1) * t) * s;
        int pos = atomicAdd(&g_cnt[i], 1);
        if (pos < CAP) g_list[i * CAP + pos] = e;
    }
}

// ---------------------------------------------------------------------------
// phi via tensor cores (tf32 3x split): phi = silu(s@W1+b1)@W2+b2
// 16 atoms/block (one m16 tile), 8 warps; A/H pre-split into hi/lo smem so
// the inner loops are pure LDS+LDG+MMA.  Warp n-slices: 16 (pass1)/48 (pass2).
// ---------------------------------------------------------------------------
__global__ void __launch_bounds__(256)
k_phi_mma(int c, const float* __restrict__ B1, const float* __restrict__ B2)
{
    __shared__ float sAh[MT][PAD], sAl[MT][PAD];
    __shared__ float sHh[MT][PAD], sHl[MT][PAD];
    int tid  = threadIdx.x;
    int wid  = tid >> 5, lane = tid & 31;
    int gid  = lane >> 2, tg = lane & 3;
    int abase = blockIdx.x * MT;

    const float* W1hi = g_w1hi + c * F * F;
    const float* W1lo = g_w1lo + c * F * F;
    const float* W2hi = g_w2hi + c * F * F3;
    const float* W2lo = g_w2lo + c * F * F3;

    // stage + split A once per block
    for (int x = tid; x < MT * F; x += 256) {
        int r = x >> 7, col = x & 127;
        float v = g_s[(abase + r) * F + col];
        unsigned h = tf32_cvt(v);
        sAh[r][col] = __uint_as_float(h);
        sAl[r][col] = __uint_as_float(tf32_cvt(v - __uint_as_float(h)));
    }
    __syncthreads();

    // ---- pass 1: H = silu(S @ W1 + b1); warp covers n in [wid*16, wid*16+16)
    {
        int nb = wid * 16;
        float acc[2][4];
        #pragma unroll
        for (int nt = 0; nt < 2; nt++)
            #pragma unroll
            for (int q = 0; q < 4; q++) acc[nt][q] = 0.0f;

        for (int k0 = 0; k0 < F; k0 += 8) {
            unsigned ah0 = __float_as_uint(sAh[gid][k0 + tg]);
            unsigned ah1 = __float_as_uint(sAh[gid + 8][k0 + tg]);
            unsigned ah2 = __float_as_uint(sAh[gid][k0 + tg + 4]);
            unsigned ah3 = __float_as_uint(sAh[gid + 8][k0 + tg + 4]);
            unsigned al0 = __float_as_uint(sAl[gid][k0 + tg]);
            unsigned al1 = __float_as_uint(sAl[gid + 8][k0 + tg]);
            unsigned al2 = __float_as_uint(sAl[gid][k0 + tg + 4]);
            unsigned al3 = __float_as_uint(sAl[gid + 8][k0 + tg + 4]);
            #pragma unroll
            for (int nt = 0; nt < 2; nt++) {
                int n = nb + nt * 8 + gid;
                unsigned bh0 = __float_as_uint(W1hi[(k0 + tg) * F + n]);
                unsigned bh1 = __float_as_uint(W1hi[(k0 + tg + 4) * F + n]);
                unsigned bl0 = __float_as_uint(W1lo[(k0 + tg) * F + n]);
                unsigned bl1 = __float_as_uint(W1lo[(k0 + tg + 4) * F + n]);
                mma_tf32(acc[nt], ah0, ah1, ah2, ah3, bh0, bh1);
                mma_tf32(acc[nt], al0, al1, al2, al3, bh0, bh1);
                mma_tf32(acc[nt], ah0, ah1, ah2, ah3, bl0, bl1);
            }
        }
        #pragma unroll
        for (int nt = 0; nt < 2; nt++) {
            int n = nb + nt * 8 + 2 * tg;
            float b0 = B1[n], b1v = B1[n + 1];
            float h00 = silu(acc[nt][0] + b0);
            float h01 = silu(acc[nt][1] + b1v);
            float h10 = silu(acc[nt][2] + b0);
            float h11 = silu(acc[nt][3] + b1v);
            unsigned t0 = tf32_cvt(h00), t1 = tf32_cvt(h01);
            unsigned t2 = tf32_cvt(h10), t3 = tf32_cvt(h11);
            sHh[gid][n]         = __uint_as_float(t0);
            sHh[gid][n + 1]     = __uint_as_float(t1);
            sHh[gid + 8][n]     = __uint_as_float(t2);
            sHh[gid + 8][n + 1] = __uint_as_float(t3);
            sHl[gid][n]         = __uint_as_float(tf32_cvt(h00 - __uint_as_float(t0)));
            sHl[gid][n + 1]     = __uint_as_float(tf32_cvt(h01 - __uint_as_float(t1)));
            sHl[gid + 8][n]     = __uint_as_float(tf32_cvt(h10 - __uint_as_float(t2)));
            sHl[gid + 8][n + 1] = __uint_as_float(tf32_cvt(h11 - __uint_as_float(t3)));
        }
    }
    __syncthreads();

    // ---- pass 2: PHI = H @ W2 + b2; warp covers n in [wid*48, wid*48+48)
    {
        int nb = wid * 48;
        float acc[6][4];
        #pragma unroll
        for (int nt = 0; nt < 6; nt++)
            #pragma unroll
            for (int q = 0; q < 4; q++) acc[nt][q] = 0.0f;

        for (int k0 = 0; k0 < F; k0 += 8) {
            unsigned ah0 = __float_as_uint(sHh[gid][k0 + tg]);
            unsigned ah1 = __float_as_uint(sHh[gid + 8][k0 + tg]);
            unsigned ah2 = __float_as_uint(sHh[gid][k0 + tg + 4]);
            unsigned ah3 = __float_as_uint(sHh[gid + 8][k0 + tg + 4]);
            unsigned al0 = __float_as_uint(sHl[gid][k0 + tg]);
            unsigned al1 = __float_as_uint(sHl[gid + 8][k0 + tg]);
            unsigned al2 = __float_as_uint(sHl[gid][k0 + tg + 4]);
            unsigned al3 = __float_as_uint(sHl[gid + 8][k0 + tg + 4]);
            #pragma unroll
            for (int nt = 0; nt < 6; nt++) {
                int n = nb + nt * 8 + gid;
                unsigned bh0 = __float_as_uint(W2hi[(k0 + tg) * F3 + n]);
                unsigned bh1 = __float_as_uint(W2hi[(k0 + tg + 4) * F3 + n]);
                unsigned bl0 = __float_as_uint(W2lo[(k0 + tg) * F3 + n]);
                unsigned bl1 = __float_as_uint(W2lo[(k0 + tg + 4) * F3 + n]);
                mma_tf32(acc[nt], ah0, ah1, ah2, ah3, bh0, bh1);
                mma_tf32(acc[nt], al0, al1, al2, al3, bh0, bh1);
                mma_tf32(acc[nt], ah0, ah1, ah2, ah3, bl0, bl1);
            }
        }
        #pragma unroll
        for (int nt = 0; nt < 6; nt++) {
            int n = nb + nt * 8 + 2 * tg;
            float b0 = B2[n], b1v = B2[n + 1];
            int a = abase + gid;
            g_phi[a * F3 + n]           = acc[nt][0] + b0;
            g_phi[a * F3 + n + 1]       = acc[nt][1] + b1v;
            g_phi[(a + 8) * F3 + n]     = acc[nt][2] + b0;
            g_phi[(a + 8) * F3 + n + 1] = acc[nt][3] + b1v;
        }
    }
}

// ---------------------------------------------------------------------------
// message pass over CSR buckets (R4-exact)
// ---------------------------------------------------------------------------
__global__ void __launch_bounds__(128)
k_msg(const float* __restrict__ RW, const float* __restrict__ RB,
      const int* __restrict__ nbrs)
{
    __shared__ float rw2s[NRBF * F];   // ch2 weights, 10 KB
    __shared__ int   sj  [CAP];
    __shared__ float senv[CAP];
    __shared__ float sux [CAP];
    __shared__ float suy [CAP];
    __shared__ float suz [CAP];
    __shared__ float srbf[CAP][NRBF];

    int f = threadIdx.x;

    unsigned long long rw01[NRBF];
    #pragma unroll
    for (int q = 0; q < NRBF; q++)
        rw01[q] = pk2(RW[q * F3 + f], RW[q * F3 + F + f]);
    for (int idx = f; idx < NRBF * F; idx += 128) {
        int q = idx >> 7, ff = idx & 127;
        rw2s[idx] = RW[q * F3 + 2 * F + ff];
    }
    float rb0 = RB[f], rb1 = RB[F + f], rb2 = RB[2 * F + f];

    int abase = blockIdx.x * TAM;

    for (int it = 0; it < TAM; it++) {
        int a = abase + it;
        int n = g_cnt[a];
        if (n > CAP) n = CAP;

        __syncthreads();   // prev iter smem reads done; also covers rw2s fill
        if (f < n) {
            int e = g_list[a * CAP + f];
            sj  [f] = nbrs[2 * e + 1];
            senv[f] = g_env[e];
            sux [f] = g_unit[3 * e];
            suy [f] = g_unit[3 * e + 1];
            suz [f] = g_unit[3 * e + 2];
            const float4* rp = (const float4*)(g_rbf + e * NRBF);
            float4* dst = (float4*)&srbf[f][0];
            #pragma unroll
            for (int x = 0; x < NRBF / 4; x++) dst[x] = rp[x];
        }
        __syncthreads();

        float ds = 0.0f, dv0 = 0.0f, dv1 = 0.0f, dv2 = 0.0f;
        float pj0 = 0.f, pj1 = 0.f, pj2 = 0.f, vj0 = 0.f, vj1 = 0.f, vj2 = 0.f;
        if (n > 0) {
            int j = sj[0];
            const float* pj = g_phi + j * F3;
            pj0 = pj[f]; pj1 = pj[F + f]; pj2 = pj[2 * F + f];
            const float* vj = g_v + j * F3 + f * 3;
            vj0 = vj[0]; vj1 = vj[1]; vj2 = vj[2];
        }
        for (int k = 0; k < n; k++) {
            float npj0 = 0.f, npj1 = 0.f, npj2 = 0.f, nvj0 = 0.f, nvj1 = 0.f, nvj2 = 0.f;
            if (k + 1 < n) {
                int jn = sj[k + 1];
                const float* pj = g_phi + jn * F3;
                npj0 = pj[f]; npj1 = pj[F + f]; npj2 = pj[2 * F + f];
                const float* vj = g_v + jn * F3 + f * 3;
                nvj0 = vj[0]; nvj1 = vj[1]; nvj2 = vj[2];
            }
            float env = senv[k];
            unsigned long long wA = pk2(env * rb0, env * rb1);
            unsigned long long wB = pk2(0.0f, 0.0f);
            float w2a = env * rb2, w2b = 0.0f;
            #pragma unroll
            for (int q = 0; q < NRBF; q += 2) {
                float r0 = srbf[k][q];
                float r1 = srbf[k][q + 1];
                FFMA2(wA, pk2(r0, r0), rw01[q]);
                FFMA2(wB, pk2(r1, r1), rw01[q + 1]);
                w2a = fmaf(r0, rw2s[q * F + f], w2a);
                w2b = fmaf(r1, rw2s[(q + 1) * F + f], w2b);
            }
            float2 xa = upk2(wA), xb = upk2(wB);
            float w0v = xa.x + xb.x;
            float w1v = xa.y + xb.y;
            float w2v = w2a + w2b;

            float sp0 = pj0 * w0v;
            float sp1 = pj1 * w1v;
            float sp2 = pj2 * w2v;
            ds += sp1;
            dv0 += sp2 * sux[k] + sp0 * vj0;
            dv1 += sp2 * suy[k] + sp0 * vj1;
            dv2 += sp2 * suz[k] + sp0 * vj2;

            pj0 = npj0; pj1 = npj1; pj2 = npj2;
            vj0 = nvj0; vj1 = nvj1; vj2 = nvj2;
        }
        g_ds[a * F + f] = ds;
        g_dv[a * F3 + f * 3]     = dv0;
        g_dv[a * F3 + f * 3 + 1] = dv1;
        g_dv[a * F3 + f * 3 + 2] = dv2;
    }
}

// ---------------------------------------------------------------------------
// update block (R4-exact: 256 threads = 2 halves x 8 atoms)
// ---------------------------------------------------------------------------
__global__ void __launch_bounds__(256)
k_upd(const float* __restrict__ U,  const float* __restrict__ V,
      const float* __restrict__ W1, const float* __restrict__ B1,
      const float* __restrict__ W2, const float* __restrict__ B2)
{
    int tid  = threadIdx.x;
    int half = tid >> 7;
    int f    = tid & 127;
    int a0   = blockIdx.x * (2 * TA) + half * TA;

    __shared__ float svT[2][F][3][TA];    // 24 KB
    __shared__ float stT[2][2 * F][TA];   // 16 KB (reused as shT after W1 pass)
    float (*shT)[F][TA] = (float (*)[F][TA])&stT[0][0][0];

    float snew[TA];
    #pragma unroll
    for (int t = 0; t < TA; t++) {
        int a = a0 + t;
        float s1 = g_s[a * F + f] + g_ds[a * F + f];
        snew[t]         = s1;
        stT[half][f][t] = s1;
        #pragma unroll
        for (int d = 0; d < 3; d++)
            svT[half][f][d][t] = g_v[a * F3 + f * 3 + d] + g_dv[a * F3 + f * 3 + d];
    }
    __syncthreads();

    unsigned long long ua[3][TA / 2], wa[3][TA / 2];
    #pragma unroll
    for (int d = 0; d < 3; d++)
        #pragma unroll
        for (int p = 0; p < TA / 2; p++) { ua[d][p] = 0ULL; wa[d][p] = 0ULL; }
    for (int g = 0; g < F; g++) {
        float Ug = U[g * F + f], Vg = V[g * F + f];
        unsigned long long Up = pk2(Ug, Ug), Vp = pk2(Vg, Vg);
        #pragma unroll
        for (int d = 0; d < 3; d++) {
            const unsigned long long* row = (const unsigned long long*)&svT[half][g][d][0];
            #pragma unroll
            for (int p = 0; p < TA / 2; p++) {
                unsigned long long r = row[p];
                FFMA2(ua[d][p], r, Up);
                FFMA2(wa[d][p], r, Vp);
            }
        }
    }
    float u[TA][3], uw[TA];
    #pragma unroll
    for (int p = 0; p < TA / 2; p++) {
        float wv[2][3];
        #pragma unroll
        for (int d = 0; d < 3; d++) {
            float2 xu = upk2(ua[d][p]);
            float2 xw = upk2(wa[d][p]);
            u[2 * p][d] = xu.x; u[2 * p + 1][d] = xu.y;
            wv[0][d] = xw.x;    wv[1][d] = xw.y;
        }
        #pragma unroll
        for (int h = 0; h < 2; h++) {
            int t = 2 * p + h;
            float n2 = wv[h][0] * wv[h][0] + wv[h][1] * wv[h][1] + wv[h][2] * wv[h][2];
            stT[half][F + f][t] = sqrtf(n2 + 1e-15f);
            uw[t] = u[t][0] * wv[h][0] + u[t][1] * wv[h][1] + u[t][2] * wv[h][2];
        }
    }
    __syncthreads();

    unsigned long long hacc[TA / 2];
    {
        unsigned long long b = pk2(B1[f], B1[f]);
        #pragma unroll
        for (int p = 0; p < TA / 2; p++) hacc[p] = b;
    }
    for (int r = 0; r < 2 * F; r++) {
        float wv = W1[r * F + f];
        unsigned long long ww = pk2(wv, wv);
        const unsigned long long* row = (const unsigned long long*)&stT[half][r][0];
        #pragma unroll
        for (int p = 0; p < TA / 2; p++) FFMA2(hacc[p], row[p], ww);
    }
    __syncthreads();
    #pragma unroll
    for (int p = 0; p < TA / 2; p++) {
        float2 x = upk2(hacc[p]);
        shT[half][f][2 * p]     = silu(x.x);
        shT[half][f][2 * p + 1] = silu(x.y);
    }
    __syncthreads();

    unsigned long long p0[TA / 2], p1[TA / 2], p2[TA / 2];
    {
        unsigned long long b0 = pk2(B2[f], B2[f]);
        unsigned long long b1 = pk2(B2[F + f], B2[F + f]);
        unsigned long long b2 = pk2(B2[2 * F + f], B2[2 * F + f]);
        #pragma unroll
        for (int p = 0; p < TA / 2; p++) { p0[p] = b0; p1[p] = b1; p2[p] = b2; }
    }
    for (int g = 0; g < F; g++) {
        const float* wr = W2 + g * F3;
        unsigned long long w0 = pk2(wr[f], wr[f]);
        unsigned long long w1 = pk2(wr[F + f], wr[F + f]);
        unsigned long long w2 = pk2(wr[2 * F + f], wr[2 * F + f]);
        const unsigned long long* row = (const unsigned long long*)&shT[half][g][0];
        #pragma unroll
        for (int p = 0; p < TA / 2; p++) {
            FFMA2(p0[p], row[p], w0);
            FFMA2(p1[p], row[p], w1);
            FFMA2(p2[p], row[p], w2);
        }
    }
    #pragma unroll
    for (int p = 0; p < TA / 2; p++) {
        float2 avv = upk2(p0[p]), asv = upk2(p1[p]), ass = upk2(p2[p]);
        #pragma unroll
        for (int h = 0; h < 2; h++) {
            int t = 2 * p + h;
            int a = a0 + t;
            float a_vv = h ? avv.y : avv.x;
            float a_sv = h ? asv.y : asv.x;
            float a_ss = h ? ass.y : ass.x;
            g_s[a * F + f] = snew[t] + uw[t] * a_sv + a_ss;
            #pragma unroll
            for (int d = 0; d < 3; d++)
                g_v[a * F3 + f * 3 + d] = svT[half][f][d][t] + u[t][d] * a_vv;
        }
    }
}

// ---------------------------------------------------------------------------
// readout: 16 atoms per block
// ---------------------------------------------------------------------------
#define TR 16

__global__ void k_zero_out(float* out)
{
    int t = threadIdx.x;
    if (t < NMOLS) out[t] = 0.0f;
}

__global__ void __launch_bounds__(128)
k_readout(const float* __restrict__ W1, const float* __restrict__ B1,
          const float* __restrict__ W2, const float* __restrict__ B2,
          const int* __restrict__ mol, float* __restrict__ out)
{
    int tid  = threadIdx.x;
    int half = tid >> 6;
    int t    = tid & 63;
    int ab   = blockIdx.x * TR;

    __shared__ float ssT[F][TR];
    __shared__ float red[TR][64];

    for (int x = tid; x < TR * F; x += 128) {
        int aa = x >> 7, ff = x & 127;
        ssT[ff][aa] = g_s[(ab + aa) * F + ff];
    }
    __syncthreads();

    unsigned long long acc[4];
    {
        unsigned long long b = pk2(B1[t], B1[t]);
        #pragma unroll
        for (int p = 0; p < 4; p++) acc[p] = b;
    }
    for (int g = 0; g < F; g++) {
        float w = W1[g * 64 + t];
        unsigned long long ww = pk2(w, w);
        const unsigned long long* row = (const unsigned long long*)&ssT[g][half * 8];
        #pragma unroll
        for (int p = 0; p < 4; p++) FFMA2(acc[p], row[p], ww);
    }
    float w2v = W2[t];
    #pragma unroll
    for (int p = 0; p < 4; p++) {
        float2 x = upk2(acc[p]);
        red[half * 8 + 2 * p][t]     = silu(x.x) * w2v;
        red[half * 8 + 2 * p + 1][t] = silu(x.y) * w2v;
    }
    __syncthreads();

    if (tid < TR) {
        float e = B2[0];
        #pragma unroll
        for (int q = 0; q < 64; q++) e += red[tid][q];
        atomicAdd(&out[mol[ab + tid]], e);
    }
}

// ---------------------------------------------------------------------------
// launch
// ---------------------------------------------------------------------------
extern "C" void kernel_launch(void* const* d_in, const int* in_sizes, int n_in,
                              void* d_out, int out_size)
{
    const float* xyz    = (const float*)d_in[0];
    const float* emb    = (const float*)d_in[1];
    const float* msg_w1 = (const float*)d_in[2];
    const float* msg_b1 = (const float*)d_in[3];
    const float* msg_w2 = (const float*)d_in[4];
    const float* msg_b2 = (const float*)d_in[5];
    const float* rbf_w  = (const float*)d_in[6];
    const float* rbf_b  = (const float*)d_in[7];
    const float* upd_u  = (const float*)d_in[8];
    const float* upd_v  = (const float*)d_in[9];
    const float* upd_w1 = (const float*)d_in[10];
    const float* upd_b1 = (const float*)d_in[11];
    const float* upd_w2 = (const float*)d_in[12];
    const float* upd_b2 = (const float*)d_in[13];
    const float* ro_w1  = (const float*)d_in[14];
    const float* ro_b1  = (const float*)d_in[15];
    const float* ro_w2  = (const float*)d_in[16];
    const float* ro_b2  = (const float*)d_in[17];
    const int*   z      = (const int*)d_in[18];
    const int*   nbrs   = (const int*)d_in[19];
    const int*   mol    = (const int*)d_in[20];
    float*       out    = (float*)d_out;

    int E = in_sizes[19] / 2;

    k_init <<<NATOMS, 128>>>(emb, z);
    k_split<<<(NCONV * F * F3 + 255) / 256, 256>>>(msg_w1, msg_w2);
    k_edges<<<(E + 255) / 256, 256>>>(xyz, nbrs, E);

    for (int c = 0; c < NCONV; c++) {
        k_phi_mma<<<NATOMS / MT, 256>>>(c, msg_b1 + c * F, msg_b2 + c * F3);
        k_msg<<<NATOMS / TAM, 128>>>(rbf_w + c * NRBF * F3, rbf_b + c * F3, nbrs);
        k_upd<<<NATOMS / (2 * TA), 256>>>(upd_u  + c * F * F,     upd_v  + c * F * F,
                                          upd_w1 + c * 2 * F * F, upd_b1 + c * F,
                                          upd_w2 + c * F * F3,    upd_b2 + c * F3);
    }

    k_zero_out<<<1, 128>>>(out);
    k_readout <<<NATOMS / TR, 128>>>(ro_w1, ro_b1, ro_w2, ro_b2, mol, out);
}

// round 14
// speedup vs baseline: 1.1581x; 1.1581x over previous
#include <cuda_runtime.h>
#include <math.h>

// ---- problem constants ----
#define F      128
#define F3     384
#define NRBF   20
#define NATOMS 8000
#define NEDGES 160000
#define NMOLS  100
#define NCONV  3
#define CUTOFF 5.0f

#define TA  8    // atoms per half in phi/upd kernels (16 per block)
#define TAM 4    // atoms per block in msg kernel
#define CAP 64   // max active edges per destination atom

// ---- device scratch ----
__device__ float g_s   [NATOMS * F];
__device__ float g_v   [NATOMS * F3];
__device__ float g_ds  [NATOMS * F];
__device__ float g_dv  [NATOMS * F3];
__device__ float g_phi [NATOMS * F3];
__device__ float g_rbf [NEDGES * NRBF];   // env-premultiplied
__device__ float g_env [NEDGES];
__device__ float g_unit[NEDGES * 3];
__device__ int   g_cnt [NATOMS];
__device__ int   g_list[NATOMS * CAP];

__device__ __forceinline__ float silu(float x) { return x / (1.0f + __expf(-x)); }

// packed fp32x2 helpers
#define FFMA2(acc, a, b) asm("fma.rn.f32x2 %0, %1, %2, %0;" : "+l"(acc) : "l"(a), "l"(b))
__device__ __forceinline__ unsigned long long pk2(float x, float y) {
    unsigned long long r; asm("mov.b64 %0, {%1, %2};" : "=l"(r) : "f"(x), "f"(y)); return r;
}
__device__ __forceinline__ float2 upk2(unsigned long long v) {
    float2 o; asm("mov.b64 {%0, %1}, %2;" : "=f"(o.x), "=f"(o.y) : "l"(v)); return o;
}

// ---------------------------------------------------------------------------
// init: s = emb[z], v = 0, CSR counters = 0, out = 0 (folded zero_out)
// ---------------------------------------------------------------------------
__global__ void k_init(const float* __restrict__ emb, const int* __restrict__ z,
                       float* __restrict__ out)
{
    int a = blockIdx.x, f = threadIdx.x;
    g_s[a * F + f] = emb[z[a] * F + f];
    int b = a * F3 + f * 3;
    g_v[b] = 0.0f; g_v[b + 1] = 0.0f; g_v[b + 2] = 0.0f;
    if (f == 0) g_cnt[a] = 0;
    if (a == 0 && f < NMOLS) out[f] = 0.0f;
}

// ---------------------------------------------------------------------------
// edge geometry + CSR build.  rbf sines via Chebyshev recurrence:
// sin((k+1)x) = 2cos(x)sin(kx) - sin((k-1)x)   (2 MUFU instead of 20)
// ---------------------------------------------------------------------------
__global__ void k_edges(const float* __restrict__ xyz, const int* __restrict__ nbrs, int E)
{
    int e = blockIdx.x * 256 + threadIdx.x;
    if (e >= E) return;
    int i = nbrs[2 * e], j = nbrs[2 * e + 1];
    float rx = xyz[3 * j]     - xyz[3 * i];
    float ry = xyz[3 * j + 1] - xyz[3 * i + 1];
    float rz = xyz[3 * j + 2] - xyz[3 * i + 2];
    float d  = sqrtf(rx * rx + ry * ry + rz * rz);
    float inv = 1.0f / d;
    float t = d * (1.0f / CUTOFF);
    if (d <= CUTOFF) {
        float c1 = cospif(t);
        float s1 = sinpif(t);
        float env = 0.5f * (c1 + 1.0f);
        g_env[e] = env;
        g_unit[3 * e]     = rx * inv;
        g_unit[3 * e + 1] = ry * inv;
        g_unit[3 * e + 2] = rz * inv;
        float s = env * inv;
        float twoc = 2.0f * c1;
        float sk_1 = 0.0f;      // sin(0)
        float sk   = s1;        // sin(pi t)
        g_rbf[e * NRBF] = sk * s;
        #pragma unroll
        for (int k = 1; k < NRBF; k++) {
            float sk1 = twoc * sk - sk_1;
            sk_1 = sk;
            sk = sk1;
            g_rbf[e * NRBF + k] = sk * s;
        }
        int pos = atomicAdd(&g_cnt[i], 1);
        if (pos < CAP) g_list[i * CAP + pos] = e;
    }
}

// ---------------------------------------------------------------------------
// phi = silu(s @ W1 + b1) @ W2 + b2   (256 threads = 2 halves, 16 atoms/block)
// ---------------------------------------------------------------------------
__global__ void __launch_bounds__(256)
k_phi(const float* __restrict__ W1, const float* __restrict__ B1,
      const float* __restrict__ W2, const float* __restrict__ B2)
{
    int tid  = threadIdx.x;
    int half = tid >> 7;
    int f    = tid & 127;
    int a0   = blockIdx.x * (2 * TA) + half * TA;

    __shared__ float ssT[2][F][TA];
    __shared__ float hhT[2][F][TA];

    #pragma unroll
    for (int t = 0; t < TA; t++) ssT[half][f][t] = g_s[(a0 + t) * F + f];
    __syncthreads();

    unsigned long long acc[TA / 2];
    {
        unsigned long long b = pk2(B1[f], B1[f]);
        #pragma unroll
        for (int p = 0; p < TA / 2; p++) acc[p] = b;
    }
    for (int g = 0; g < F; g++) {
        float w = W1[g * F + f];
        unsigned long long ww = pk2(w, w);
        const unsigned long long* row = (const unsigned long long*)&ssT[half][g][0];
        #pragma unroll
        for (int p = 0; p < TA / 2; p++) FFMA2(acc[p], row[p], ww);
    }
    #pragma unroll
    for (int p = 0; p < TA / 2; p++) {
        float2 x = upk2(acc[p]);
        hhT[half][f][2 * p]     = silu(x.x);
        hhT[half][f][2 * p + 1] = silu(x.y);
    }
    __syncthreads();

    unsigned long long p0[TA / 2], p1[TA / 2], p2[TA / 2];
    {
        unsigned long long b0 = pk2(B2[f], B2[f]);
        unsigned long long b1 = pk2(B2[F + f], B2[F + f]);
        unsigned long long b2 = pk2(B2[2 * F + f], B2[2 * F + f]);
        #pragma unroll
        for (int p = 0; p < TA / 2; p++) { p0[p] = b0; p1[p] = b1; p2[p] = b2; }
    }
    for (int g = 0; g < F; g++) {
        const float* w = W2 + g * F3;
        unsigned long long w0 = pk2(w[f], w[f]);
        unsigned long long w1 = pk2(w[F + f], w[F + f]);
        unsigned long long w2 = pk2(w[2 * F + f], w[2 * F + f]);
        const unsigned long long* row = (const unsigned long long*)&hhT[half][g][0];
        #pragma unroll
        for (int p = 0; p < TA / 2; p++) {
            FFMA2(p0[p], row[p], w0);
            FFMA2(p1[p], row[p], w1);
            FFMA2(p2[p], row[p], w2);
        }
    }
    #pragma unroll
    for (int p = 0; p < TA / 2; p++) {
        float2 x0 = upk2(p0[p]), x1 = upk2(p1[p]), x2 = upk2(p2[p]);
        int a = a0 + 2 * p;
        g_phi[a * F3 + f]               = x0.x;
        g_phi[(a + 1) * F3 + f]         = x0.y;
        g_phi[a * F3 + F + f]           = x1.x;
        g_phi[(a + 1) * F3 + F + f]     = x1.y;
        g_phi[a * F3 + 2 * F + f]       = x2.x;
        g_phi[(a + 1) * F3 + 2 * F + f] = x2.y;
    }
}

// ---------------------------------------------------------------------------
// message pass over CSR buckets (R4-exact)
// ---------------------------------------------------------------------------
__global__ void __launch_bounds__(128)
k_msg(const float* __restrict__ RW, const float* __restrict__ RB,
      const int* __restrict__ nbrs)
{
    __shared__ float rw2s[NRBF * F];   // ch2 weights, 10 KB
    __shared__ int   sj  [CAP];
    __shared__ float senv[CAP];
    __shared__ float sux [CAP];
    __shared__ float suy [CAP];
    __shared__ float suz [CAP];
    __shared__ float srbf[CAP][NRBF];

    int f = threadIdx.x;

    unsigned long long rw01[NRBF];
    #pragma unroll
    for (int q = 0; q < NRBF; q++)
        rw01[q] = pk2(RW[q * F3 + f], RW[q * F3 + F + f]);
    for (int idx = f; idx < NRBF * F; idx += 128) {
        int q = idx >> 7, ff = idx & 127;
        rw2s[idx] = RW[q * F3 + 2 * F + ff];
    }
    float rb0 = RB[f], rb1 = RB[F + f], rb2 = RB[2 * F + f];

    int abase = blockIdx.x * TAM;

    for (int it = 0; it < TAM; it++) {
        int a = abase + it;
        int n = g_cnt[a];
        if (n > CAP) n = CAP;

        __syncthreads();   // prev iter smem reads done; also covers rw2s fill
        if (f < n) {
            int e = g_list[a * CAP + f];
            sj  [f] = nbrs[2 * e + 1];
            senv[f] = g_env[e];
            sux [f] = g_unit[3 * e];
            suy [f] = g_unit[3 * e + 1];
            suz [f] = g_unit[3 * e + 2];
            const float4* rp = (const float4*)(g_rbf + e * NRBF);
            float4* dst = (float4*)&srbf[f][0];
            #pragma unroll
            for (int x = 0; x < NRBF / 4; x++) dst[x] = rp[x];
        }
        __syncthreads();

        float ds = 0.0f, dv0 = 0.0f, dv1 = 0.0f, dv2 = 0.0f;
        float pj0 = 0.f, pj1 = 0.f, pj2 = 0.f, vj0 = 0.f, vj1 = 0.f, vj2 = 0.f;
        if (n > 0) {
            int j = sj[0];
            const float* pj = g_phi + j * F3;
            pj0 = pj[f]; pj1 = pj[F + f]; pj2 = pj[2 * F + f];
            const float* vj = g_v + j * F3 + f * 3;
            vj0 = vj[0]; vj1 = vj[1]; vj2 = vj[2];
        }
        for (int k = 0; k < n; k++) {
            float npj0 = 0.f, npj1 = 0.f, npj2 = 0.f, nvj0 = 0.f, nvj1 = 0.f, nvj2 = 0.f;
            if (k + 1 < n) {
                int jn = sj[k + 1];
                const float* pj = g_phi + jn * F3;
                npj0 = pj[f]; npj1 = pj[F + f]; npj2 = pj[2 * F + f];
                const float* vj = g_v + jn * F3 + f * 3;
                nvj0 = vj[0]; nvj1 = vj[1]; nvj2 = vj[2];
            }
            float env = senv[k];
            unsigned long long wA = pk2(env * rb0, env * rb1);
            unsigned long long wB = pk2(0.0f, 0.0f);
            float w2a = env * rb2, w2b = 0.0f;
            #pragma unroll
            for (int q = 0; q < NRBF; q += 2) {
                float r0 = srbf[k][q];
                float r1 = srbf[k][q + 1];
                FFMA2(wA, pk2(r0, r0), rw01[q]);
                FFMA2(wB, pk2(r1, r1), rw01[q + 1]);
                w2a = fmaf(r0, rw2s[q * F + f], w2a);
                w2b = fmaf(r1, rw2s[(q + 1) * F + f], w2b);
            }
            float2 xa = upk2(wA), xb = upk2(wB);
            float w0v = xa.x + xb.x;
            float w1v = xa.y + xb.y;
            float w2v = w2a + w2b;

            float sp0 = pj0 * w0v;
            float sp1 = pj1 * w1v;
            float sp2 = pj2 * w2v;
            ds += sp1;
            dv0 += sp2 * sux[k] + sp0 * vj0;
            dv1 += sp2 * suy[k] + sp0 * vj1;
            dv2 += sp2 * suz[k] + sp0 * vj2;

            pj0 = npj0; pj1 = npj1; pj2 = npj2;
            vj0 = nvj0; vj1 = nvj1; vj2 = nvj2;
        }
        g_ds[a * F + f] = ds;
        g_dv[a * F3 + f * 3]     = dv0;
        g_dv[a * F3 + f * 3 + 1] = dv1;
        g_dv[a * F3 + f * 3 + 2] = dv2;
    }
}

// ---------------------------------------------------------------------------
// update block (R4-exact: 256 threads = 2 halves x 8 atoms)
// ---------------------------------------------------------------------------
__global__ void __launch_bounds__(256)
k_upd(const float* __restrict__ U,  const float* __restrict__ V,
      const float* __restrict__ W1, const float* __restrict__ B1,
      const float* __restrict__ W2, const float* __restrict__ B2)
{
    int tid  = threadIdx.x;
    int half = tid >> 7;
    int f    = tid & 127;
    int a0   = blockIdx.x * (2 * TA) + half * TA;

    __shared__ float svT[2][F][3][TA];    // 24 KB
    __shared__ float stT[2][2 * F][TA];   // 16 KB (reused as shT after W1 pass)
    float (*shT)[F][TA] = (float (*)[F][TA])&stT[0][0][0];

    float snew[TA];
    #pragma unroll
    for (int t = 0; t < TA; t++) {
        int a = a0 + t;
        float s1 = g_s[a * F + f] + g_ds[a * F + f];
        snew[t]         = s1;
        stT[half][f][t] = s1;
        #pragma unroll
        for (int d = 0; d < 3; d++)
            svT[half][f][d][t] = g_v[a * F3 + f * 3 + d] + g_dv[a * F3 + f * 3 + d];
    }
    __syncthreads();

    unsigned long long ua[3][TA / 2], wa[3][TA / 2];
    #pragma unroll
    for (int d = 0; d < 3; d++)
        #pragma unroll
        for (int p = 0; p < TA / 2; p++) { ua[d][p] = 0ULL; wa[d][p] = 0ULL; }
    for (int g = 0; g < F; g++) {
        float Ug = U[g * F + f], Vg = V[g * F + f];
        unsigned long long Up = pk2(Ug, Ug), Vp = pk2(Vg, Vg);
        #pragma unroll
        for (int d = 0; d < 3; d++) {
            const unsigned long long* row = (const unsigned long long*)&svT[half][g][d][0];
            #pragma unroll
            for (int p = 0; p < TA / 2; p++) {
                unsigned long long r = row[p];
                FFMA2(ua[d][p], r, Up);
                FFMA2(wa[d][p], r, Vp);
            }
        }
    }
    float u[TA][3], uw[TA];
    #pragma unroll
    for (int p = 0; p < TA / 2; p++) {
        float wv[2][3];
        #pragma unroll
        for (int d = 0; d < 3; d++) {
            float2 xu = upk2(ua[d][p]);
            float2 xw = upk2(wa[d][p]);
            u[2 * p][d] = xu.x; u[2 * p + 1][d] = xu.y;
            wv[0][d] = xw.x;    wv[1][d] = xw.y;
        }
        #pragma unroll
        for (int h = 0; h < 2; h++) {
            int t = 2 * p + h;
            float n2 = wv[h][0] * wv[h][0] + wv[h][1] * wv[h][1] + wv[h][2] * wv[h][2];
            stT[half][F + f][t] = sqrtf(n2 + 1e-15f);
            uw[t] = u[t][0] * wv[h][0] + u[t][1] * wv[h][1] + u[t][2] * wv[h][2];
        }
    }
    __syncthreads();

    unsigned long long hacc[TA / 2];
    {
        unsigned long long b = pk2(B1[f], B1[f]);
        #pragma unroll
        for (int p = 0; p < TA / 2; p++) hacc[p] = b;
    }
    for (int r = 0; r < 2 * F; r++) {
        float wv = W1[r * F + f];
        unsigned long long ww = pk2(wv, wv);
        const unsigned long long* row = (const unsigned long long*)&stT[half][r][0];
        #pragma unroll
        for (int p = 0; p < TA / 2; p++) FFMA2(hacc[p], row[p], ww);
    }
    __syncthreads();
    #pragma unroll
    for (int p = 0; p < TA / 2; p++) {
        float2 x = upk2(hacc[p]);
        shT[half][f][2 * p]     = silu(x.x);
        shT[half][f][2 * p + 1] = silu(x.y);
    }
    __syncthreads();

    unsigned long long p0[TA / 2], p1[TA / 2], p2[TA / 2];
    {
        unsigned long long b0 = pk2(B2[f], B2[f]);
        unsigned long long b1 = pk2(B2[F + f], B2[F + f]);
        unsigned long long b2 = pk2(B2[2 * F + f], B2[2 * F + f]);
        #pragma unroll
        for (int p = 0; p < TA / 2; p++) { p0[p] = b0; p1[p] = b1; p2[p] = b2; }
    }
    for (int g = 0; g < F; g++) {
        const float* wr = W2 + g * F3;
        unsigned long long w0 = pk2(wr[f], wr[f]);
        unsigned long long w1 = pk2(wr[F + f], wr[F + f]);
        unsigned long long w2 = pk2(wr[2 * F + f], wr[2 * F + f]);
        const unsigned long long* row = (const unsigned long long*)&shT[half][g][0];
        #pragma unroll
        for (int p = 0; p < TA / 2; p++) {
            FFMA2(p0[p], row[p], w0);
            FFMA2(p1[p], row[p], w1);
            FFMA2(p2[p], row[p], w2);
        }
    }
    #pragma unroll
    for (int p = 0; p < TA / 2; p++) {
        float2 avv = upk2(p0[p]), asv = upk2(p1[p]), ass = upk2(p2[p]);
        #pragma unroll
        for (int h = 0; h < 2; h++) {
            int t = 2 * p + h;
            int a = a0 + t;
            float a_vv = h ? avv.y : avv.x;
            float a_sv = h ? asv.y : asv.x;
            float a_ss = h ? ass.y : ass.x;
            g_s[a * F + f] = snew[t] + uw[t] * a_sv + a_ss;
            #pragma unroll
            for (int d = 0; d < 3; d++)
                g_v[a * F3 + f * 3 + d] = svT[half][f][d][t] + u[t][d] * a_vv;
        }
    }
}

// ---------------------------------------------------------------------------
// readout: 16 atoms per block
// ---------------------------------------------------------------------------
#define TR 16

__global__ void __launch_bounds__(128)
k_readout(const float* __restrict__ W1, const float* __restrict__ B1,
          const float* __restrict__ W2, const float* __restrict__ B2,
          const int* __restrict__ mol, float* __restrict__ out)
{
    int tid  = threadIdx.x;
    int half = tid >> 6;
    int t    = tid & 63;
    int ab   = blockIdx.x * TR;

    __shared__ float ssT[F][TR];
    __shared__ float red[TR][64];

    for (int x = tid; x < TR * F; x += 128) {
        int aa = x >> 7, ff = x & 127;
        ssT[ff][aa] = g_s[(ab + aa) * F + ff];
    }
    __syncthreads();

    unsigned long long acc[4];
    {
        unsigned long long b = pk2(B1[t], B1[t]);
        #pragma unroll
        for (int p = 0; p < 4; p++) acc[p] = b;
    }
    for (int g = 0; g < F; g++) {
        float w = W1[g * 64 + t];
        unsigned long long ww = pk2(w, w);
        const unsigned long long* row = (const unsigned long long*)&ssT[g][half * 8];
        #pragma unroll
        for (int p = 0; p < 4; p++) FFMA2(acc[p], row[p], ww);
    }
    float w2v = W2[t];
    #pragma unroll
    for (int p = 0; p < 4; p++) {
        float2 x = upk2(acc[p]);
        red[half * 8 + 2 * p][t]     = silu(x.x) * w2v;
        red[half * 8 + 2 * p + 1][t] = silu(x.y) * w2v;
    }
    __syncthreads();

    if (tid < TR) {
        float e = B2[0];
        #pragma unroll
        for (int q = 0; q < 64; q++) e += red[tid][q];
        atomicAdd(&out[mol[ab + tid]], e);
    }
}

// ---------------------------------------------------------------------------
// launch
// ---------------------------------------------------------------------------
extern "C" void kernel_launch(void* const* d_in, const int* in_sizes, int n_in,
                              void* d_out, int out_size)
{
    const float* xyz    = (const float*)d_in[0];
    const float* emb    = (const float*)d_in[1];
    const float* msg_w1 = (const float*)d_in[2];
    const float* msg_b1 = (const float*)d_in[3];
    const float* msg_w2 = (const float*)d_in[4];
    const float* msg_b2 = (const float*)d_in[5];
    const float* rbf_w  = (const float*)d_in[6];
    const float* rbf_b  = (const float*)d_in[7];
    const float* upd_u  = (const float*)d_in[8];
    const float* upd_v  = (const float*)d_in[9];
    const float* upd_w1 = (const float*)d_in[10];
    const float* upd_b1 = (const float*)d_in[11];
    const float* upd_w2 = (const float*)d_in[12];
    const float* upd_b2 = (const float*)d_in[13];
    const float* ro_w1  = (const float*)d_in[14];
    const float* ro_b1  = (const float*)d_in[15];
    const float* ro_w2  = (const float*)d_in[16];
    const float* ro_b2  = (const float*)d_in[17];
    const int*   z      = (const int*)d_in[18];
    const int*   nbrs   = (const int*)d_in[19];
    const int*   mol    = (const int*)d_in[20];
    float*       out    = (float*)d_out;

    int E = in_sizes[19] / 2;

    k_init <<<NATOMS, 128>>>(emb, z, out);
    k_edges<<<(E + 255) / 256, 256>>>(xyz, nbrs, E);

    for (int c = 0; c < NCONV; c++) {
        k_phi<<<NATOMS / (2 * TA), 256>>>(msg_w1 + c * F * F,     msg_b1 + c * F,
                                          msg_w2 + c * F * F3,    msg_b2 + c * F3);
        k_msg<<<NATOMS / TAM, 128>>>(rbf_w + c * NRBF * F3, rbf_b + c * F3, nbrs);
        k_upd<<<NATOMS / (2 * TA), 256>>>(upd_u  + c * F * F,     upd_v  + c * F * F,
                                          upd_w1 + c * 2 * F * F, upd_b1 + c * F,
                                          upd_w2 + c * F * F3,    upd_b2 + c * F3);
    }

    k_readout<<<NATOMS / TR, 128>>>(ro_w1, ro_b1, ro_w2, ro_b2, mol, out);
}